// round 7
// baseline (speedup 1.0000x reference)
#include <cuda_runtime.h>
#include <cstdint>
#include <math_constants.h>

#define BATCH 131072
#define RPB   256              /* rows per block */
#define NPB   (BATCH / RPB)    /* 512 row blocks */

#if defined(__CUDA_ARCH_FEAT_SM103_ALL) || defined(__CUDA_ARCH_FEAT_SM100_ALL) || defined(__CUDA_ARCH_FEAT_SM101_ALL)
#define HAS_TCGEN05 1
#else
#define HAS_TCGEN05 0
#endif

// ---------------- scratch ----------------------------------------------------
__device__ float g_a1[BATCH * 128];
__device__ float g_a2[BATCH * 256];
__device__ float g_a3[BATCH * 128];
__device__ float g_psum[256 * NPB];   // column-major: [col][rowblock]
__device__ float g_psq [256 * NPB];
__device__ float g_scale[256];
__device__ float g_shift[256];
__device__ float g_wtiles[147456];    // preformatted W tiles (8192 floats each)

// ---------------- ptx helpers -------------------------------------------------
__device__ __forceinline__ uint32_t smem_u32(const void* p) {
    uint32_t a;
    asm("{ .reg .u64 t; cvta.to.shared.u64 t, %1; cvt.u32.u64 %0, t; }" : "=r"(a) : "l"(p));
    return a;
}

#if HAS_TCGEN05
__device__ __forceinline__ uint32_t elect1() {
    uint32_t p;
    asm volatile("{\n\t.reg .pred p;\n\telect.sync _|p, 0xFFFFFFFF;\n\tselp.b32 %0, 1, 0, p;\n\t}" : "=r"(p));
    return p;
}
#define TCGEN05_ALLOC(smem_addr, nCols) \
    asm volatile("tcgen05.alloc.cta_group::1.sync.aligned.shared::cta.b32 [%0], %1;" \
                 :: "r"((uint32_t)(smem_addr)), "r"((uint32_t)(nCols)) : "memory")
#define TCGEN05_DEALLOC(tmem_addr, nCols) \
    asm volatile("tcgen05.dealloc.cta_group::1.sync.aligned.b32 %0, %1;" \
                 :: "r"(tmem_addr), "r"((uint32_t)(nCols)))
#define TCGEN05_RELINQ() \
    asm volatile("tcgen05.relinquish_alloc_permit.cta_group::1.sync.aligned;")
#define TCGEN05_COMMIT(mbar_smem_addr) \
    asm volatile("tcgen05.commit.cta_group::1.mbarrier::arrive::one.shared::cluster.b64 [%0];" \
                 :: "r"((uint32_t)(mbar_smem_addr)) : "memory")
#define TCGEN05_FENCE_AFTER() \
    asm volatile("tcgen05.fence::after_thread_sync;" ::: "memory")
#define TCGEN05_FENCE_BEFORE() \
    asm volatile("tcgen05.fence::before_thread_sync;" ::: "memory")
#define TCGEN05_WAIT_LD() \
    asm volatile("tcgen05.wait::ld.sync.aligned;" ::: "memory")
#define MBARRIER_INIT(mbar_smem_addr, count) \
    asm volatile("mbarrier.init.shared.b64 [%0], %1;" \
                 :: "r"((uint32_t)(mbar_smem_addr)), "r"((uint32_t)(count)) : "memory")
#define MBARRIER_WAIT_PARITY(mbar_smem_addr, phase_parity) do { \
    uint32_t _mbar = (uint32_t)(mbar_smem_addr); \
    uint32_t _parity = (uint32_t)(phase_parity); \
    uint32_t _done; \
    asm volatile("{\n\t.reg .pred p;\n\t" \
        "mbarrier.try_wait.parity.acquire.cta.shared::cta.b64 p, [%1], %2;\n\t" \
        "selp.b32 %0, 1, 0, p;\n\t}" \
        : "=r"(_done) : "r"(_mbar), "r"(_parity) : "memory"); \
    if (!_done) { \
        asm volatile("{\n\t.reg .pred P1;\n\t" \
            "WAIT_LOOP_%=:\n\t" \
            "mbarrier.try_wait.parity.acquire.cta.shared::cta.b64 P1, [%0], %1, 0x989680;\n\t" \
            "@P1 bra.uni WAIT_DONE_%=;\n\t" \
            "bra.uni WAIT_LOOP_%=;\n\t" \
            "WAIT_DONE_%=:\n\t}" \
            :: "r"(_mbar), "r"(_parity) : "memory"); \
    } \
} while (0)
#define TCGEN05_LD_32X32B_X32(r, tmem_addr) \
    asm volatile("tcgen05.ld.sync.aligned.32x32b.x32.b32 " \
        "{%0, %1, %2, %3, %4, %5, %6, %7, " \
        " %8, %9, %10, %11, %12, %13, %14, %15, " \
        " %16, %17, %18, %19, %20, %21, %22, %23, " \
        " %24, %25, %26, %27, %28, %29, %30, %31}, [%32];" \
        : "=r"((r)[0]),  "=r"((r)[1]),  "=r"((r)[2]),  "=r"((r)[3]), \
          "=r"((r)[4]),  "=r"((r)[5]),  "=r"((r)[6]),  "=r"((r)[7]), \
          "=r"((r)[8]),  "=r"((r)[9]),  "=r"((r)[10]), "=r"((r)[11]), \
          "=r"((r)[12]), "=r"((r)[13]), "=r"((r)[14]), "=r"((r)[15]), \
          "=r"((r)[16]), "=r"((r)[17]), "=r"((r)[18]), "=r"((r)[19]), \
          "=r"((r)[20]), "=r"((r)[21]), "=r"((r)[22]), "=r"((r)[23]), \
          "=r"((r)[24]), "=r"((r)[25]), "=r"((r)[26]), "=r"((r)[27]), \
          "=r"((r)[28]), "=r"((r)[29]), "=r"((r)[30]), "=r"((r)[31]) \
        : "r"(tmem_addr))

__device__ __forceinline__ uint64_t sdesc(uint32_t addr) {
    return ((uint64_t)2 << 61) | ((uint64_t)1 << 46) | ((uint64_t)64 << 32) |
           ((uint64_t)1 << 16) | ((uint64_t)(addr >> 4) & 0x3FFF);
}
__device__ __forceinline__ void mma_tf32_ss(uint32_t d, uint64_t ad, uint64_t bd,
                                            uint32_t idesc, uint32_t en) {
    asm volatile("{\n\t.reg .pred p;\n\tsetp.ne.u32 p, %4, 0;\n\t"
        "tcgen05.mma.cta_group::1.kind::tf32 [%0], %1, %2, %3, {%5, %5, %5, %5}, p;\n\t}"
        :: "r"(d), "l"(ad), "l"(bd), "r"(idesc), "r"(en), "r"(0u) : "memory");
}
#endif // HAS_TCGEN05

#define SW128(o) ((o) ^ (((o) >> 3) & 0x70))

// smem layout (after 1KB alignment pad):
//   0      stage0: A0h A0l A1h A1l Bh Bl (16KB each) = 96KB
//   98304  stage1 (96KB)
//   196608 epilogue staging: 64 rows x 67 floats (17.4KB)
//   214016 sSc(1K) 215040 sSh(1K) 216064 sB(512) 216576 redS(1K) 217600 redQ(1K)
#define STAGE_SZ 98304
#define EPI_OFF  196608
#define GEMM_SMEM (220 * 1024)

// ---------------------------------------------------------------------------
__global__ void prep_w(const float* __restrict__ W, float* __restrict__ dst,
                       int Kdim, int N)
{
    const int ch = blockIdx.x, cb = blockIdx.y;
    const int NCH = gridDim.x;
    char* tile = (char*)(dst + (size_t)(cb * NCH + ch) * 8192);
    const int tid = threadIdx.x;
#pragma unroll
    for (int e = 0; e < 16; e++) {
        int idx = tid + e * 256;
        int n = idx >> 5, kk = idx & 31;
        int k = ch * 32 + kk;
        float v = (k < Kdim) ? W[(size_t)k * N + cb * 128 + n] : 0.f;
        uint32_t hb; asm("cvt.rna.tf32.f32 %0, %1;" : "=r"(hb) : "f"(v));
        float lo = v - __uint_as_float(hb);
        uint32_t off = SW128((uint32_t)(n * 128 + kk * 4));
        *(uint32_t*)(tile + off)         = hb;
        *(float*)   (tile + 16384 + off) = lo;
    }
}

#if HAS_TCGEN05
// ---------------------------------------------------------------------------
// Epilogue for one 256x128 block from TMEM half p: bias add, coalesced store
// to C, per-block column stats. 8 passes of 64x64 slabs through 17KB staging.
// ---------------------------------------------------------------------------
__device__ __forceinline__ void epilogue_block(
    char* bp, uint32_t tmem, int p, int b, int N, int col0,
    float* __restrict__ C, int tid, int wid, int lane)
{
    float* stage = (float*)(bp + EPI_OFF);
    float* sB    = (float*)(bp + 216064);
    float* redS  = (float*)(bp + 216576);
    float* redQ  = (float*)(bp + 217600);
    const int row0 = b * RPB;
    const int rw = wid & 3, cg = wid >> 2;
    const int colS = tid & 63, rg = tid >> 6;
#pragma unroll 1
    for (int h = 0; h < 2; h++) {
        float sAcc = 0.f, qAcc = 0.f;
#pragma unroll 1
        for (int t = 0; t < 2; t++) {
#pragma unroll 1
            for (int q = 0; q < 2; q++) {
                if ((rw >> 1) == q) {
                    uint32_t regs[32];
                    TCGEN05_LD_32X32B_X32(regs, tmem + p * 256 + t * 128 + h * 64 + cg * 32);
                    TCGEN05_WAIT_LD();
                    TCGEN05_FENCE_BEFORE();
                    const int srow = (rw & 1) * 32 + lane;
#pragma unroll
                    for (int j = 0; j < 32; j++) {
                        float v = __uint_as_float(regs[j]) + sB[h * 64 + cg * 32 + j];
                        stage[srow * 67 + cg * 32 + j] = v;
                    }
                }
                __syncthreads();
#pragma unroll 4
                for (int rr = 0; rr < 16; rr++) {
                    int r = rg * 16 + rr;
                    float v = stage[r * 67 + colS];
                    C[(size_t)(row0 + t * 128 + q * 64 + r) * N + col0 + h * 64 + colS] = v;
                    sAcc += v; qAcc = fmaf(v, v, qAcc);
                }
                __syncthreads();
            }
        }
        redS[rg * 64 + colS] = sAcc;
        redQ[rg * 64 + colS] = qAcc;
        __syncthreads();
        if (tid < 64) {
            float s = redS[tid] + redS[64 + tid] + redS[128 + tid] + redS[192 + tid];
            float q = redQ[tid] + redQ[64 + tid] + redQ[128 + tid] + redQ[192 + tid];
            int c = col0 + h * 64 + tid;
            g_psum[(size_t)c * NPB + b] = s;
            g_psq [(size_t)c * NPB + b] = q;
        }
        __syncthreads();
    }
}
#endif

// ---------------------------------------------------------------------------
// Persistent GEMM: C[B,N] = act(A[B,K]) @ W[K,N] + bias. Each CTA loops over
// row blocks (stride gridDim.x). TMEM halves by block parity; epilogue of
// block s-1 overlaps the async MMAs of block s.
// ---------------------------------------------------------------------------
template<int KDIM, bool ACT>
__global__ __launch_bounds__(256, 1)
void gemm_tc(const float* __restrict__ A, const float* __restrict__ W,
             const float* __restrict__ wt, const float* __restrict__ bias,
             float* __restrict__ C, int N)
{
#if HAS_TCGEN05
    constexpr int NCH = (KDIM + 31) / 32;
    extern __shared__ char dsm[];
    const uint32_t sb0 = smem_u32(dsm);
    const uint32_t pad = ((sb0 + 1023) & ~1023u) - sb0;
    char* bp = dsm + pad;
    const uint32_t sbu = sb0 + pad;

    float* sSc = (float*)(bp + 214016);
    float* sSh = (float*)(bp + 215040);
    float* sB  = (float*)(bp + 216064);

    __shared__ uint64_t s_stmb[2];
    __shared__ uint64_t s_blkmb[2];
    __shared__ uint32_t s_tptr;
    const uint32_t stMb[2]  = { smem_u32(&s_stmb[0]),  smem_u32(&s_stmb[1]) };
    const uint32_t blkMb[2] = { smem_u32(&s_blkmb[0]), smem_u32(&s_blkmb[1]) };

    const int tid  = threadIdx.x;
    const int wid  = tid >> 5;
    const int lane = tid & 31;
    const int col0 = blockIdx.y * 128;

    if (ACT) {
        for (int i = tid; i < KDIM; i += 256) { sSc[i] = g_scale[i]; sSh[i] = g_shift[i]; }
    }
    for (int i = tid; i < 128; i += 256) sB[i] = bias[col0 + i];
    if (tid == 0) {
        MBARRIER_INIT(stMb[0], 1);  MBARRIER_INIT(stMb[1], 1);
        MBARRIER_INIT(blkMb[0], 1); MBARRIER_INIT(blkMb[1], 1);
    }
    if (wid == 0) TCGEN05_ALLOC(smem_u32(&s_tptr), 512);
    __syncthreads();
    const uint32_t tmem = s_tptr;

    const uint32_t IDESC = (1u << 4) | (2u << 7) | (2u << 10) | (16u << 17) | (8u << 24);

    int cidx = 0;       // global chunk counter (stage pipeline)
    int s = 0;          // block sequence counter
    int prevb = -1;

    for (int b = blockIdx.x; b < NPB; b += gridDim.x, s++) {
        const int p = s & 1;
        const int row0 = b * RPB;

        for (int ch = 0; ch < NCH; ch++) {
            const int st = cidx & 1, use = cidx >> 1;
            if (use >= 1) { MBARRIER_WAIT_PARITY(stMb[st], (use - 1) & 1); }

            char* ps = bp + st * STAGE_SZ;
            const int k0 = ch * 32;

            // B copy (preformatted 32KB tile, L2-hot)
            {
                const float4* src = (const float4*)(wt + (size_t)(blockIdx.y * NCH + ch) * 8192);
                float4* dst = (float4*)(ps + 65536);
#pragma unroll
                for (int i = 0; i < 8; i++) dst[tid + i * 256] = src[tid + i * 256];
            }
            // A fill (two 128-row tiles)
#pragma unroll
            for (int t = 0; t < 2; t++) {
                char* pAh = ps + t * 32768;
                char* pAl = pAh + 16384;
                const int rbase = row0 + t * 128;
                if (KDIM % 4 == 0) {
#pragma unroll
                    for (int e = 0; e < 4; e++) {
                        int f = tid + e * 256;
                        int m = f >> 3, kq = f & 7;
                        float4 v4 = *(const float4*)(A + (size_t)(rbase + m) * KDIM + k0 + kq * 4);
                        float vv[4] = {v4.x, v4.y, v4.z, v4.w};
                        uint32_t hi[4]; float lo[4];
#pragma unroll
                        for (int u = 0; u < 4; u++) {
                            float v = vv[u];
                            if (ACT) {
                                int k = k0 + kq * 4 + u;
                                v = fmaf(v, sSc[k], sSh[k]);
                                v = v > 0.f ? v : 0.2f * v;
                            }
                            asm("cvt.rna.tf32.f32 %0, %1;" : "=r"(hi[u]) : "f"(v));
                            lo[u] = v - __uint_as_float(hi[u]);
                        }
                        uint32_t off = SW128((uint32_t)(m * 128 + kq * 16));
                        *(uint4*)(pAh + off)  = make_uint4(hi[0], hi[1], hi[2], hi[3]);
                        *(float4*)(pAl + off) = make_float4(lo[0], lo[1], lo[2], lo[3]);
                    }
                } else {
#pragma unroll
                    for (int i = 0; i < 16; i++) {
                        int idx = tid + i * 256;
                        int m = idx >> 5, kk = idx & 31, k = k0 + kk;
                        float v = 0.f;
                        if (k < KDIM) {
                            v = A[(size_t)(rbase + m) * KDIM + k];
                            if (ACT) {
                                v = fmaf(v, sSc[k], sSh[k]);
                                v = v > 0.f ? v : 0.2f * v;
                            }
                        }
                        uint32_t hb; asm("cvt.rna.tf32.f32 %0, %1;" : "=r"(hb) : "f"(v));
                        float lo = v - __uint_as_float(hb);
                        uint32_t off = SW128((uint32_t)(m * 128 + kk * 4));
                        *(uint32_t*)(pAh + off) = hb;
                        *(float*)   (pAl + off) = lo;
                    }
                }
            }
            asm volatile("fence.proxy.async.shared::cta;" ::: "memory");
            __syncthreads();

            if (wid == 0 && elect1()) {
                const uint32_t sbase = sbu + st * STAGE_SZ;
                uint64_t bdh = sdesc(sbase + 65536), bdl = sdesc(sbase + 81920);
#pragma unroll
                for (int t = 0; t < 2; t++) {
                    uint64_t adh = sdesc(sbase + t * 32768);
                    uint64_t adl = sdesc(sbase + t * 32768 + 16384);
                    uint32_t dofs = tmem + p * 256 + t * 128;
#pragma unroll
                    for (int ks = 0; ks < 4; ks++) {
                        uint32_t en0 = (ch == 0 && ks == 0) ? 0u : 1u;
                        mma_tf32_ss(dofs, adh + ks * 2, bdh + ks * 2, IDESC, en0);
                        mma_tf32_ss(dofs, adh + ks * 2, bdl + ks * 2, IDESC, 1u);
                        mma_tf32_ss(dofs, adl + ks * 2, bdh + ks * 2, IDESC, 1u);
                    }
                }
                TCGEN05_COMMIT(stMb[st]);
                if (ch == NCH - 1) TCGEN05_COMMIT(blkMb[p]);
            }
            cidx++;
        }

        // epilogue of previous block, overlapped with this block's async MMAs
        if (s >= 1) {
            MBARRIER_WAIT_PARITY(blkMb[(s - 1) & 1], ((s - 1) >> 1) & 1);
            TCGEN05_FENCE_AFTER();
            epilogue_block(bp, tmem, (s - 1) & 1, prevb, N, col0, C, tid, wid, lane);
        }
        prevb = b;
    }

    // drain: epilogue of the final block
    if (s >= 1) {
        MBARRIER_WAIT_PARITY(blkMb[(s - 1) & 1], ((s - 1) >> 1) & 1);
        TCGEN05_FENCE_AFTER();
        epilogue_block(bp, tmem, (s - 1) & 1, prevb, N, col0, C, tid, wid, lane);
    }

    if (wid == 0) { TCGEN05_RELINQ(); TCGEN05_DEALLOC(tmem, 512); }

#else
    // ======================= FFMA fallback (plain sm_103 pass) ============
    extern __shared__ char dsm[];
    float (*As)[128] = (float(*)[128])dsm;
    float (*Ws)[128] = (float(*)[128])(dsm + 8192);
    float* sSc = (float*)(dsm + 16384);
    float* sSh = (float*)(dsm + 17408);

    const int tid  = threadIdx.x;
    const int col0 = blockIdx.y * 128;

    if (ACT) {
        for (int i = tid; i < KDIM; i += 256) { sSc[i] = g_scale[i]; sSh[i] = g_shift[i]; }
        __syncthreads();
    }
    const int ty = tid >> 4;
    const int tx = tid & 15;
    float bj[8];
#pragma unroll
    for (int j = 0; j < 8; j++) bj[j] = bias[col0 + tx * 8 + j];

    for (int b = blockIdx.x; b < NPB; b += gridDim.x) {
        float cs[8], cq[8];
#pragma unroll
        for (int j = 0; j < 8; j++) { cs[j] = 0.f; cq[j] = 0.f; }

#pragma unroll 1
        for (int rt = 0; rt < 2; rt++) {
            const int row0 = b * RPB + rt * 128;
            float acc[8][8];
#pragma unroll
            for (int i = 0; i < 8; i++)
#pragma unroll
                for (int j = 0; j < 8; j++) acc[i][j] = 0.f;

            for (int k0 = 0; k0 < KDIM; k0 += 16) {
#pragma unroll
                for (int l = 0; l < 8; l++) {
                    int idx = tid + l * 256;
                    int m = idx >> 4, kk = idx & 15;
                    int k = k0 + kk;
                    float v = 0.f;
                    if ((KDIM % 16 == 0) || k < KDIM) {
                        v = A[(size_t)(row0 + m) * KDIM + k];
                        if (ACT) {
                            v = fmaf(v, sSc[k], sSh[k]);
                            v = v > 0.f ? v : 0.2f * v;
                        }
                    }
                    As[kk][m] = v;
                }
#pragma unroll
                for (int l = 0; l < 8; l++) {
                    int idx = tid + l * 256;
                    int kk = idx >> 7, n = idx & 127;
                    int k = k0 + kk;
                    Ws[kk][n] = ((KDIM % 16 == 0) || k < KDIM) ? W[(size_t)k * N + col0 + n] : 0.f;
                }
                __syncthreads();
#pragma unroll
                for (int kk = 0; kk < 16; kk++) {
                    float4 a0 = *(const float4*)&As[kk][ty * 8];
                    float4 a1 = *(const float4*)&As[kk][ty * 8 + 4];
                    float4 w0 = *(const float4*)&Ws[kk][tx * 8];
                    float4 w1 = *(const float4*)&Ws[kk][tx * 8 + 4];
                    float a[8] = {a0.x, a0.y, a0.z, a0.w, a1.x, a1.y, a1.z, a1.w};
                    float w[8] = {w0.x, w0.y, w0.z, w0.w, w1.x, w1.y, w1.z, w1.w};
#pragma unroll
                    for (int i = 0; i < 8; i++)
#pragma unroll
                        for (int j = 0; j < 8; j++)
                            acc[i][j] = fmaf(a[i], w[j], acc[i][j]);
                }
                __syncthreads();
            }
#pragma unroll
            for (int i = 0; i < 8; i++) {
                float v[8];
#pragma unroll
                for (int j = 0; j < 8; j++) {
                    v[j] = acc[i][j] + bj[j];
                    cs[j] += v[j];
                    cq[j] = fmaf(v[j], v[j], cq[j]);
                }
                float* cptr = &C[(size_t)(row0 + ty * 8 + i) * N + col0 + tx * 8];
                *(float4*)cptr       = make_float4(v[0], v[1], v[2], v[3]);
                *(float4*)(cptr + 4) = make_float4(v[4], v[5], v[6], v[7]);
            }
            __syncthreads();
        }

        float* red = &As[0][0];
#pragma unroll
        for (int j = 0; j < 8; j++) red[ty * 128 + tx * 8 + j] = cs[j];
        __syncthreads();
        if (tid < 128) {
            float s = 0.f;
#pragma unroll
            for (int r = 0; r < 16; r++) s += red[r * 128 + tid];
            g_psum[(size_t)(col0 + tid) * NPB + b] = s;
        }
        __syncthreads();
#pragma unroll
        for (int j = 0; j < 8; j++) red[ty * 128 + tx * 8 + j] = cq[j];
        __syncthreads();
        if (tid < 128) {
            float s = 0.f;
#pragma unroll
            for (int r = 0; r < 16; r++) s += red[r * 128 + tid];
            g_psq[(size_t)(col0 + tid) * NPB + b] = s;
        }
        __syncthreads();
    }
#endif
}

// ---------------------------------------------------------------------------
__global__ void stats_kernel(const float* __restrict__ gamma,
                             const float* __restrict__ beta, int N)
{
    __shared__ float ss[128], qq[128];
    const int c = blockIdx.x;
    const int t = threadIdx.x;
    const float* bs = g_psum + (size_t)c * NPB;
    const float* bq = g_psq  + (size_t)c * NPB;
    float s = bs[t] + bs[t + 128] + bs[t + 256] + bs[t + 384];
    float q = bq[t] + bq[t + 128] + bq[t + 256] + bq[t + 384];
    ss[t] = s; qq[t] = q;
    __syncthreads();
    for (int off = 64; off > 0; off >>= 1) {
        if (t < off) { ss[t] += ss[t + off]; qq[t] += qq[t + off]; }
        __syncthreads();
    }
    if (t == 0) {
        float mean = ss[0] * (1.0f / (float)BATCH);
        float var  = qq[0] * (1.0f / (float)BATCH) - mean * mean;
        float inv  = rsqrtf(var + 1e-5f);
        float scl  = gamma[c] * inv;
        g_scale[c] = scl;
        g_shift[c] = beta[c] - mean * scl;
    }
}

// ---------------------------------------------------------------------------
__global__ __launch_bounds__(128)
void final_kernel(const float* __restrict__ W4, const float* __restrict__ b4,
                  const float* __restrict__ U, float* __restrict__ out)
{
    __shared__ float w4s[128 * 25];
    __shared__ float b4s[25];
    __shared__ float sc[128], sh[128];
    __shared__ __align__(16) float us[128 * 25];

    const int tid  = threadIdx.x;
    const int row0 = blockIdx.x * 128;
    const int row  = row0 + tid;

    for (int i = tid; i < 128 * 25; i += 128) w4s[i] = W4[i];
    if (tid < 25) b4s[tid] = b4[tid];
    sc[tid] = g_scale[tid];
    sh[tid] = g_shift[tid];
    __syncthreads();

    float lgt[25];
#pragma unroll
    for (int j = 0; j < 25; j++) lgt[j] = b4s[j];

    const float* arow = g_a3 + (size_t)row * 128;
    for (int k = 0; k < 128; k += 4) {
        float4 a4 = *(const float4*)(arow + k);
        float hv[4] = {a4.x, a4.y, a4.z, a4.w};
#pragma unroll
        for (int t = 0; t < 4; t++) {
            float h = fmaf(hv[t], sc[k + t], sh[k + t]);
            h = h > 0.f ? h : 0.2f * h;
#pragma unroll
            for (int j = 0; j < 25; j++)
                lgt[j] = fmaf(h, w4s[(k + t) * 25 + j], lgt[j]);
        }
    }

    unsigned mask = 0x1FFFFFFu;
#pragma unroll 1
    for (int s = 0; s < 15; s++) {
        __syncthreads();
        const float4* ub4 = (const float4*)(U + ((size_t)s * BATCH + row0) * 25);
        float4* us4 = (float4*)us;
        for (int i = tid; i < 800; i += 128) us4[i] = ub4[i];
        __syncthreads();

        float best = -CUDART_INF_F;
        int bi = __ffs(mask) - 1;
#pragma unroll
        for (int j = 0; j < 25; j++) {
            if (mask & (1u << j)) {
                float uu = us[tid * 25 + j];
                float nz = -__logf(-__logf(uu));
                float v  = lgt[j] + nz;
                if (v > best) { best = v; bi = j; }
            }
        }
        mask &= ~(1u << bi);
        out[(size_t)row * 15 + s] = (float)bi / 24.0f;
    }
}

// ---------------------------------------------------------------------------
extern "C" void kernel_launch(void* const* d_in, const int* in_sizes, int n_in,
                              void* d_out, int out_size)
{
    const float* z   = (const float*)d_in[0];
    const float* u   = (const float*)d_in[1];
    const float* W1  = (const float*)d_in[2];
    const float* b1  = (const float*)d_in[3];
    const float* g1  = (const float*)d_in[4];
    const float* be1 = (const float*)d_in[5];
    const float* W2  = (const float*)d_in[6];
    const float* b2  = (const float*)d_in[7];
    const float* g2  = (const float*)d_in[8];
    const float* be2 = (const float*)d_in[9];
    const float* W3  = (const float*)d_in[10];
    const float* b3  = (const float*)d_in[11];
    const float* g3  = (const float*)d_in[12];
    const float* be3 = (const float*)d_in[13];
    const float* W4  = (const float*)d_in[14];
    const float* b4  = (const float*)d_in[15];
    float* out = (float*)d_out;

    float *a1, *a2, *a3, *wt;
    cudaGetSymbolAddress((void**)&a1, g_a1);
    cudaGetSymbolAddress((void**)&a2, g_a2);
    cudaGetSymbolAddress((void**)&a3, g_a3);
    cudaGetSymbolAddress((void**)&wt, g_wtiles);
    float* wt1 = wt;            // L1: 2 tiles
    float* wt2 = wt + 16384;    // L2: 8 tiles
    float* wt3 = wt + 81920;    // L3: 8 tiles

    cudaFuncSetAttribute(gemm_tc<50,  false>, cudaFuncAttributeMaxDynamicSharedMemorySize, GEMM_SMEM);
    cudaFuncSetAttribute(gemm_tc<128, true >, cudaFuncAttributeMaxDynamicSharedMemorySize, GEMM_SMEM);
    cudaFuncSetAttribute(gemm_tc<256, true >, cudaFuncAttributeMaxDynamicSharedMemorySize, GEMM_SMEM);

    prep_w<<<dim3(2, 1), 256>>>(W1, wt1, 50, 128);
    prep_w<<<dim3(4, 2), 256>>>(W2, wt2, 128, 256);
    prep_w<<<dim3(8, 1), 256>>>(W3, wt3, 256, 128);

    gemm_tc<50,  false><<<dim3(148, 1), 256, GEMM_SMEM>>>(z,  W1, wt1, b1, a1, 128);
    stats_kernel<<<128, 128>>>(g1, be1, 128);
    gemm_tc<128, true ><<<dim3(74,  2), 256, GEMM_SMEM>>>(a1, W2, wt2, b2, a2, 256);
    stats_kernel<<<256, 128>>>(g2, be2, 256);
    gemm_tc<256, true ><<<dim3(148, 1), 256, GEMM_SMEM>>>(a2, W3, wt3, b3, a3, 128);
    stats_kernel<<<128, 128>>>(g3, be3, 128);
    final_kernel<<<1024, 128>>>(W4, b4, u, out);
}

// round 8
// speedup vs baseline: 1.1070x; 1.1070x over previous
#include <cuda_runtime.h>
#include <cstdint>
#include <math_constants.h>

#define BATCH 131072
#define RPB   256              /* rows per CTA */
#define NPB   (BATCH / RPB)    /* 512 row blocks */

#if defined(__CUDA_ARCH_FEAT_SM103_ALL) || defined(__CUDA_ARCH_FEAT_SM100_ALL) || defined(__CUDA_ARCH_FEAT_SM101_ALL)
#define HAS_TCGEN05 1
#else
#define HAS_TCGEN05 0
#endif

// ---------------- scratch ----------------------------------------------------
__device__ float g_a1[BATCH * 128];
__device__ float g_a2[BATCH * 256];
__device__ float g_a3[BATCH * 128];
__device__ float g_psum[256 * NPB];   // column-major: [col][rowblock]
__device__ float g_psq [256 * NPB];
__device__ float g_scale[256];
__device__ float g_shift[256];
__device__ float g_wtiles[147456];    // preformatted W tiles (8192 floats each)

// ---------------- ptx helpers -------------------------------------------------
__device__ __forceinline__ uint32_t smem_u32(const void* p) {
    uint32_t a;
    asm("{ .reg .u64 t; cvta.to.shared.u64 t, %1; cvt.u32.u64 %0, t; }" : "=r"(a) : "l"(p));
    return a;
}

#if HAS_TCGEN05
__device__ __forceinline__ uint32_t elect1() {
    uint32_t p;
    asm volatile("{\n\t.reg .pred p;\n\telect.sync _|p, 0xFFFFFFFF;\n\tselp.b32 %0, 1, 0, p;\n\t}" : "=r"(p));
    return p;
}
#define TCGEN05_ALLOC(smem_addr, nCols) \
    asm volatile("tcgen05.alloc.cta_group::1.sync.aligned.shared::cta.b32 [%0], %1;" \
                 :: "r"((uint32_t)(smem_addr)), "r"((uint32_t)(nCols)) : "memory")
#define TCGEN05_DEALLOC(tmem_addr, nCols) \
    asm volatile("tcgen05.dealloc.cta_group::1.sync.aligned.b32 %0, %1;" \
                 :: "r"(tmem_addr), "r"((uint32_t)(nCols)))
#define TCGEN05_RELINQ() \
    asm volatile("tcgen05.relinquish_alloc_permit.cta_group::1.sync.aligned;")
#define TCGEN05_COMMIT(mbar_smem_addr) \
    asm volatile("tcgen05.commit.cta_group::1.mbarrier::arrive::one.shared::cluster.b64 [%0];" \
                 :: "r"((uint32_t)(mbar_smem_addr)) : "memory")
#define TCGEN05_FENCE_AFTER() \
    asm volatile("tcgen05.fence::after_thread_sync;" ::: "memory")
#define TCGEN05_FENCE_BEFORE() \
    asm volatile("tcgen05.fence::before_thread_sync;" ::: "memory")
#define TCGEN05_WAIT_LD() \
    asm volatile("tcgen05.wait::ld.sync.aligned;" ::: "memory")
#define MBARRIER_INIT(mbar_smem_addr, count) \
    asm volatile("mbarrier.init.shared.b64 [%0], %1;" \
                 :: "r"((uint32_t)(mbar_smem_addr)), "r"((uint32_t)(count)) : "memory")
#define MBARRIER_WAIT_PARITY(mbar_smem_addr, phase_parity) do { \
    uint32_t _mbar = (uint32_t)(mbar_smem_addr); \
    uint32_t _parity = (uint32_t)(phase_parity); \
    uint32_t _done; \
    asm volatile("{\n\t.reg .pred p;\n\t" \
        "mbarrier.try_wait.parity.acquire.cta.shared::cta.b64 p, [%1], %2;\n\t" \
        "selp.b32 %0, 1, 0, p;\n\t}" \
        : "=r"(_done) : "r"(_mbar), "r"(_parity) : "memory"); \
    if (!_done) { \
        asm volatile("{\n\t.reg .pred P1;\n\t" \
            "WAIT_LOOP_%=:\n\t" \
            "mbarrier.try_wait.parity.acquire.cta.shared::cta.b64 P1, [%0], %1, 0x989680;\n\t" \
            "@P1 bra.uni WAIT_DONE_%=;\n\t" \
            "bra.uni WAIT_LOOP_%=;\n\t" \
            "WAIT_DONE_%=:\n\t}" \
            :: "r"(_mbar), "r"(_parity) : "memory"); \
    } \
} while (0)
#define TCGEN05_LD_32X32B_X32(r, tmem_addr) \
    asm volatile("tcgen05.ld.sync.aligned.32x32b.x32.b32 " \
        "{%0, %1, %2, %3, %4, %5, %6, %7, " \
        " %8, %9, %10, %11, %12, %13, %14, %15, " \
        " %16, %17, %18, %19, %20, %21, %22, %23, " \
        " %24, %25, %26, %27, %28, %29, %30, %31}, [%32];" \
        : "=r"((r)[0]),  "=r"((r)[1]),  "=r"((r)[2]),  "=r"((r)[3]), \
          "=r"((r)[4]),  "=r"((r)[5]),  "=r"((r)[6]),  "=r"((r)[7]), \
          "=r"((r)[8]),  "=r"((r)[9]),  "=r"((r)[10]), "=r"((r)[11]), \
          "=r"((r)[12]), "=r"((r)[13]), "=r"((r)[14]), "=r"((r)[15]), \
          "=r"((r)[16]), "=r"((r)[17]), "=r"((r)[18]), "=r"((r)[19]), \
          "=r"((r)[20]), "=r"((r)[21]), "=r"((r)[22]), "=r"((r)[23]), \
          "=r"((r)[24]), "=r"((r)[25]), "=r"((r)[26]), "=r"((r)[27]), \
          "=r"((r)[28]), "=r"((r)[29]), "=r"((r)[30]), "=r"((r)[31]) \
        : "r"(tmem_addr))

__device__ __forceinline__ uint64_t sdesc(uint32_t addr) {
    return ((uint64_t)2 << 61) | ((uint64_t)1 << 46) | ((uint64_t)64 << 32) |
           ((uint64_t)1 << 16) | ((uint64_t)(addr >> 4) & 0x3FFF);
}
__device__ __forceinline__ void mma_tf32_ss(uint32_t d, uint64_t ad, uint64_t bd,
                                            uint32_t idesc, uint32_t en) {
    asm volatile("{\n\t.reg .pred p;\n\tsetp.ne.u32 p, %4, 0;\n\t"
        "tcgen05.mma.cta_group::1.kind::tf32 [%0], %1, %2, %3, {%5, %5, %5, %5}, p;\n\t}"
        :: "r"(d), "l"(ad), "l"(bd), "r"(idesc), "r"(en), "r"(0u) : "memory");
}
#endif // HAS_TCGEN05

#define SW128(o) ((o) ^ (((o) >> 3) & 0x70))

// smem layout (after 1KB alignment pad):
//   0      stage0: A0h A0l A1h A1l Bh Bl (16KB each) = 96KB
//   98304  stage1 (96KB)
//   epilogue: 4 staging slabs of 128x65 floats at wg*49152 (reuse stages)
//   196608 sSc(1K) 197632 sSh(1K) 198656 sB(512) 199168 redS(2K) 201216 redQ(2K)
#define STAGE_SZ 98304
#define GEMM_SMEM (208 * 1024)

// ---------------------------------------------------------------------------
__global__ void prep_w(const float* __restrict__ W, float* __restrict__ dst,
                       int Kdim, int N)
{
    const int ch = blockIdx.x, cb = blockIdx.y;
    const int NCH = gridDim.x;
    char* tile = (char*)(dst + (size_t)(cb * NCH + ch) * 8192);
    const int tid = threadIdx.x;
#pragma unroll
    for (int e = 0; e < 16; e++) {
        int idx = tid + e * 256;
        int n = idx >> 5, kk = idx & 31;
        int k = ch * 32 + kk;
        float v = (k < Kdim) ? W[(size_t)k * N + cb * 128 + n] : 0.f;
        uint32_t hb; asm("cvt.rna.tf32.f32 %0, %1;" : "=r"(hb) : "f"(v));
        float lo = v - __uint_as_float(hb);
        uint32_t off = SW128((uint32_t)(n * 128 + kk * 4));
        *(uint32_t*)(tile + off)         = hb;
        *(float*)   (tile + 16384 + off) = lo;
    }
}

// ---------------------------------------------------------------------------
// GEMM: 512 threads, M=256/CTA, two-stage double buffer, tcgen05 3xTF32.
// Epilogue: 4 warpgroups handle the 4 (row-tile, col-half) quadrants in
// parallel with private staging slabs and named barriers.
// ---------------------------------------------------------------------------
template<int KDIM, bool ACT>
__global__ __launch_bounds__(512, 1)
void gemm_tc(const float* __restrict__ A, const float* __restrict__ W,
             const float* __restrict__ wt, const float* __restrict__ bias,
             float* __restrict__ C, int N)
{
#if HAS_TCGEN05
    constexpr int NCH = (KDIM + 31) / 32;
    extern __shared__ char dsm[];
    const uint32_t sb0 = smem_u32(dsm);
    const uint32_t pad = ((sb0 + 1023) & ~1023u) - sb0;
    char* bp = dsm + pad;
    const uint32_t sbu = sb0 + pad;

    float* sSc  = (float*)(bp + 196608);
    float* sSh  = (float*)(bp + 197632);
    float* sB   = (float*)(bp + 198656);
    float* redS = (float*)(bp + 199168);
    float* redQ = (float*)(bp + 201216);

    __shared__ uint64_t s_mbar[2];
    __shared__ uint32_t s_tptr;
    const uint32_t mbA[2] = { smem_u32(&s_mbar[0]), smem_u32(&s_mbar[1]) };

    const int tid  = threadIdx.x;
    const int wid  = tid >> 5;
    const int lane = tid & 31;
    const int row0 = blockIdx.x * RPB;
    const int col0 = blockIdx.y * 128;

    if (ACT) {
        for (int i = tid; i < KDIM; i += 512) { sSc[i] = g_scale[i]; sSh[i] = g_shift[i]; }
    }
    for (int i = tid; i < 128; i += 512) sB[i] = bias[col0 + i];
    if (tid == 0) { MBARRIER_INIT(mbA[0], 1); MBARRIER_INIT(mbA[1], 1); }
    if (wid == 0) TCGEN05_ALLOC(smem_u32(&s_tptr), 256);
    __syncthreads();
    const uint32_t tmem = s_tptr;

    const uint32_t IDESC = (1u << 4) | (2u << 7) | (2u << 10) | (16u << 17) | (8u << 24);

    for (int ch = 0; ch < NCH; ch++) {
        const int st  = ch & 1;
        const int use = ch >> 1;
        if (use >= 1) { MBARRIER_WAIT_PARITY(mbA[st], (use - 1) & 1); }

        char* ps = bp + st * STAGE_SZ;
        const int k0 = ch * 32;

        // ---- B copy: preformatted 32KB tile ----
        {
            const float4* src = (const float4*)(wt + (size_t)(blockIdx.y * NCH + ch) * 8192);
            float4* dst = (float4*)(ps + 65536);
#pragma unroll
            for (int i = 0; i < 4; i++) dst[tid + i * 512] = src[tid + i * 512];
        }
        // ---- A fill: two 128-row tiles ----
#pragma unroll
        for (int t = 0; t < 2; t++) {
            char* pAh = ps + t * 32768;
            char* pAl = pAh + 16384;
            const int rbase = row0 + t * 128;
            if (KDIM % 4 == 0) {
#pragma unroll
                for (int e = 0; e < 2; e++) {
                    int f = tid + e * 512;
                    int m = f >> 3, kq = f & 7;
                    float4 v4 = *(const float4*)(A + (size_t)(rbase + m) * KDIM + k0 + kq * 4);
                    float vv[4] = {v4.x, v4.y, v4.z, v4.w};
                    uint32_t hi[4]; float lo[4];
#pragma unroll
                    for (int u = 0; u < 4; u++) {
                        float v = vv[u];
                        if (ACT) {
                            int k = k0 + kq * 4 + u;
                            v = fmaf(v, sSc[k], sSh[k]);
                            v = v > 0.f ? v : 0.2f * v;
                        }
                        asm("cvt.rna.tf32.f32 %0, %1;" : "=r"(hi[u]) : "f"(v));
                        lo[u] = v - __uint_as_float(hi[u]);
                    }
                    uint32_t off = SW128((uint32_t)(m * 128 + kq * 16));
                    *(uint4*)(pAh + off)  = make_uint4(hi[0], hi[1], hi[2], hi[3]);
                    *(float4*)(pAl + off) = make_float4(lo[0], lo[1], lo[2], lo[3]);
                }
            } else {
#pragma unroll
                for (int i = 0; i < 8; i++) {
                    int idx = tid + i * 512;
                    int m = idx >> 5, kk = idx & 31, k = k0 + kk;
                    float v = 0.f;
                    if (k < KDIM) {
                        v = A[(size_t)(rbase + m) * KDIM + k];
                        if (ACT) {
                            v = fmaf(v, sSc[k], sSh[k]);
                            v = v > 0.f ? v : 0.2f * v;
                        }
                    }
                    uint32_t hb; asm("cvt.rna.tf32.f32 %0, %1;" : "=r"(hb) : "f"(v));
                    float lo = v - __uint_as_float(hb);
                    uint32_t off = SW128((uint32_t)(m * 128 + kk * 4));
                    *(uint32_t*)(pAh + off) = hb;
                    *(float*)   (pAl + off) = lo;
                }
            }
        }
        asm volatile("fence.proxy.async.shared::cta;" ::: "memory");
        __syncthreads();

        if (wid == 0 && elect1()) {
            const uint32_t sbase = sbu + st * STAGE_SZ;
            uint64_t bdh = sdesc(sbase + 65536), bdl = sdesc(sbase + 81920);
#pragma unroll
            for (int t = 0; t < 2; t++) {
                uint64_t adh = sdesc(sbase + t * 32768);
                uint64_t adl = sdesc(sbase + t * 32768 + 16384);
                uint32_t dofs = tmem + t * 128;
#pragma unroll
                for (int ks = 0; ks < 4; ks++) {
                    uint32_t en0 = (ch == 0 && ks == 0) ? 0u : 1u;
                    mma_tf32_ss(dofs, adh + ks * 2, bdh + ks * 2, IDESC, en0);
                    mma_tf32_ss(dofs, adh + ks * 2, bdl + ks * 2, IDESC, 1u);
                    mma_tf32_ss(dofs, adl + ks * 2, bdh + ks * 2, IDESC, 1u);
                }
            }
            TCGEN05_COMMIT(mbA[st]);
        }
    }
    MBARRIER_WAIT_PARITY(mbA[(NCH - 1) & 1], ((NCH - 1) >> 1) & 1);
    TCGEN05_FENCE_AFTER();
    __syncthreads();   // fill stages are dead; reuse as epilogue staging

    // ---- epilogue: 4 warpgroups, one (row-tile t, col-half h) quadrant each
    {
        const int wg     = wid >> 2;       // 0..3
        const int rw     = wid & 3;        // subpartition (row quarter)
        const int wg_tid = tid & 127;
        const int t = wg >> 1, h = wg & 1;
        float* stage = (float*)(bp + wg * 49152);   // 128 x 65 floats

#pragma unroll
        for (int half = 0; half < 2; half++) {
            uint32_t regs[32];
            TCGEN05_LD_32X32B_X32(regs, tmem + t * 128 + h * 64 + half * 32);
            TCGEN05_WAIT_LD();
            const int row = rw * 32 + lane;
#pragma unroll
            for (int j = 0; j < 32; j++) {
                float v = __uint_as_float(regs[j]) + sB[h * 64 + half * 32 + j];
                stage[row * 65 + half * 32 + j] = v;
            }
        }
        TCGEN05_FENCE_BEFORE();
        asm volatile("bar.sync %0, 128;" :: "r"(wg + 1) : "memory");

        const int colS = wg_tid & 63, rg = wg_tid >> 6;
        float sAcc = 0.f, qAcc = 0.f;
#pragma unroll 8
        for (int it = 0; it < 64; it++) {
            int r = it * 2 + rg;
            float v = stage[r * 65 + colS];
            C[(size_t)(row0 + t * 128 + r) * N + col0 + h * 64 + colS] = v;
            sAcc += v; qAcc = fmaf(v, v, qAcc);
        }
        redS[(wg * 2 + rg) * 64 + colS] = sAcc;
        redQ[(wg * 2 + rg) * 64 + colS] = qAcc;
        __syncthreads();
        if (tid < 128) {
            const int hh = tid >> 6, col = tid & 63;
            float s = 0.f, q = 0.f;
#pragma unroll
            for (int tt = 0; tt < 2; tt++)
#pragma unroll
                for (int rr = 0; rr < 2; rr++) {
                    int g = (2 * tt + hh) * 2 + rr;
                    s += redS[g * 64 + col];
                    q += redQ[g * 64 + col];
                }
            int c = col0 + hh * 64 + col;
            g_psum[(size_t)c * NPB + blockIdx.x] = s;
            g_psq [(size_t)c * NPB + blockIdx.x] = q;
        }
    }

    __syncthreads();
    if (wid == 0) { TCGEN05_RELINQ(); TCGEN05_DEALLOC(tmem, 256); }

#else
    // ======================= FFMA fallback (plain sm_103 pass) ============
    extern __shared__ char dsm[];
    float (*As)[128] = (float(*)[128])dsm;            // 16x128
    float (*Ws)[128] = (float(*)[128])(dsm + 8192);   // 16x128
    float* sSc = (float*)(dsm + 16384);
    float* sSh = (float*)(dsm + 17408);

    const int tid  = threadIdx.x;
    const int col0 = blockIdx.y * 128;

    if (ACT) {
        for (int i = tid; i < KDIM; i += 512) { sSc[i] = g_scale[i]; sSh[i] = g_shift[i]; }
        __syncthreads();
    }
    const int ty = tid >> 4;   // 0..31
    const int tx = tid & 15;   // 0..15
    float bj[8];
#pragma unroll
    for (int j = 0; j < 8; j++) bj[j] = bias[col0 + tx * 8 + j];

    float cs[8], cq[8];
#pragma unroll
    for (int j = 0; j < 8; j++) { cs[j] = 0.f; cq[j] = 0.f; }

#pragma unroll 1
    for (int rt = 0; rt < 2; rt++) {
        const int row0 = blockIdx.x * RPB + rt * 128;
        float acc[4][8];
#pragma unroll
        for (int i = 0; i < 4; i++)
#pragma unroll
            for (int j = 0; j < 8; j++) acc[i][j] = 0.f;

        for (int k0 = 0; k0 < KDIM; k0 += 16) {
#pragma unroll
            for (int l = 0; l < 4; l++) {
                int idx = tid + l * 512;
                int m = idx >> 4, kk = idx & 15;
                int k = k0 + kk;
                float v = 0.f;
                if ((KDIM % 16 == 0) || k < KDIM) {
                    v = A[(size_t)(row0 + m) * KDIM + k];
                    if (ACT) {
                        v = fmaf(v, sSc[k], sSh[k]);
                        v = v > 0.f ? v : 0.2f * v;
                    }
                }
                As[kk][m] = v;
            }
#pragma unroll
            for (int l = 0; l < 4; l++) {
                int idx = tid + l * 512;
                int kk = idx >> 7, n = idx & 127;
                int k = k0 + kk;
                Ws[kk][n] = ((KDIM % 16 == 0) || k < KDIM) ? W[(size_t)k * N + col0 + n] : 0.f;
            }
            __syncthreads();
#pragma unroll
            for (int kk = 0; kk < 16; kk++) {
                float4 a0 = *(const float4*)&As[kk][ty * 4];
                float4 w0 = *(const float4*)&Ws[kk][tx * 8];
                float4 w1 = *(const float4*)&Ws[kk][tx * 8 + 4];
                float a[4] = {a0.x, a0.y, a0.z, a0.w};
                float w[8] = {w0.x, w0.y, w0.z, w0.w, w1.x, w1.y, w1.z, w1.w};
#pragma unroll
                for (int i = 0; i < 4; i++)
#pragma unroll
                    for (int j = 0; j < 8; j++)
                        acc[i][j] = fmaf(a[i], w[j], acc[i][j]);
            }
            __syncthreads();
        }
#pragma unroll
        for (int i = 0; i < 4; i++) {
            float v[8];
#pragma unroll
            for (int j = 0; j < 8; j++) {
                v[j] = acc[i][j] + bj[j];
                cs[j] += v[j];
                cq[j] = fmaf(v[j], v[j], cq[j]);
            }
            float* cptr = &C[(size_t)(row0 + ty * 4 + i) * N + col0 + tx * 8];
            *(float4*)cptr       = make_float4(v[0], v[1], v[2], v[3]);
            *(float4*)(cptr + 4) = make_float4(v[4], v[5], v[6], v[7]);
        }
        __syncthreads();
    }

    // column stats: red[ty][col] over 32 ty-groups
    float* red = &As[0][0];   // 32*128 floats = 16KB
#pragma unroll
    for (int j = 0; j < 8; j++) red[ty * 128 + tx * 8 + j] = cs[j];
    __syncthreads();
    if (tid < 128) {
        float s = 0.f;
#pragma unroll
        for (int r = 0; r < 32; r++) s += red[r * 128 + tid];
        g_psum[(size_t)(col0 + tid) * NPB + blockIdx.x] = s;
    }
    __syncthreads();
#pragma unroll
    for (int j = 0; j < 8; j++) red[ty * 128 + tx * 8 + j] = cq[j];
    __syncthreads();
    if (tid < 128) {
        float s = 0.f;
#pragma unroll
        for (int r = 0; r < 32; r++) s += red[r * 128 + tid];
        g_psq[(size_t)(col0 + tid) * NPB + blockIdx.x] = s;
    }
#endif
}

// ---------------------------------------------------------------------------
__global__ void stats_kernel(const float* __restrict__ gamma,
                             const float* __restrict__ beta, int N)
{
    __shared__ float ss[128], qq[128];
    const int c = blockIdx.x;
    const int t = threadIdx.x;
    const float* bs = g_psum + (size_t)c * NPB;
    const float* bq = g_psq  + (size_t)c * NPB;
    float s = bs[t] + bs[t + 128] + bs[t + 256] + bs[t + 384];
    float q = bq[t] + bq[t + 128] + bq[t + 256] + bq[t + 384];
    ss[t] = s; qq[t] = q;
    __syncthreads();
    for (int off = 64; off > 0; off >>= 1) {
        if (t < off) { ss[t] += ss[t + off]; qq[t] += qq[t + off]; }
        __syncthreads();
    }
    if (t == 0) {
        float mean = ss[0] * (1.0f / (float)BATCH);
        float var  = qq[0] * (1.0f / (float)BATCH) - mean * mean;
        float inv  = rsqrtf(var + 1e-5f);
        float scl  = gamma[c] * inv;
        g_scale[c] = scl;
        g_shift[c] = beta[c] - mean * scl;
    }
}

// ---------------------------------------------------------------------------
__global__ __launch_bounds__(256)
void final_kernel(const float* __restrict__ W4, const float* __restrict__ b4,
                  const float* __restrict__ U, float* __restrict__ out)
{
    __shared__ float w4s[128 * 25];
    __shared__ float b4s[25];
    __shared__ float sc[128], sh[128];
    __shared__ __align__(16) float us[256 * 25];

    const int tid  = threadIdx.x;
    const int row0 = blockIdx.x * 256;
    const int row  = row0 + tid;

    for (int i = tid; i < 128 * 25; i += 256) w4s[i] = W4[i];
    if (tid < 25) b4s[tid] = b4[tid];
    if (tid < 128) { sc[tid] = g_scale[tid]; sh[tid] = g_shift[tid]; }
    __syncthreads();

    float lgt[25];
#pragma unroll
    for (int j = 0; j < 25; j++) lgt[j] = b4s[j];

    const float* arow = g_a3 + (size_t)row * 128;
    for (int k = 0; k < 128; k += 4) {
        float4 a4 = *(const float4*)(arow + k);
        float hv[4] = {a4.x, a4.y, a4.z, a4.w};
#pragma unroll
        for (int t = 0; t < 4; t++) {
            float h = fmaf(hv[t], sc[k + t], sh[k + t]);
            h = h > 0.f ? h : 0.2f * h;
#pragma unroll
            for (int j = 0; j < 25; j++)
                lgt[j] = fmaf(h, w4s[(k + t) * 25 + j], lgt[j]);
        }
    }

    unsigned mask = 0x1FFFFFFu;
#pragma unroll 1
    for (int s = 0; s < 15; s++) {
        __syncthreads();
        const float4* ub4 = (const float4*)(U + ((size_t)s * BATCH + row0) * 25);
        float4* us4 = (float4*)us;
        for (int i = tid; i < 1600; i += 256) us4[i] = ub4[i];
        __syncthreads();

        float best = -CUDART_INF_F;
        int bi = __ffs(mask) - 1;
#pragma unroll
        for (int j = 0; j < 25; j++) {
            if (mask & (1u << j)) {
                float uu = us[tid * 25 + j];
                float nz = -__logf(-__logf(uu));
                float v  = lgt[j] + nz;
                if (v > best) { best = v; bi = j; }
            }
        }
        mask &= ~(1u << bi);
        out[(size_t)row * 15 + s] = (float)bi / 24.0f;
    }
}

// ---------------------------------------------------------------------------
extern "C" void kernel_launch(void* const* d_in, const int* in_sizes, int n_in,
                              void* d_out, int out_size)
{
    const float* z   = (const float*)d_in[0];
    const float* u   = (const float*)d_in[1];
    const float* W1  = (const float*)d_in[2];
    const float* b1  = (const float*)d_in[3];
    const float* g1  = (const float*)d_in[4];
    const float* be1 = (const float*)d_in[5];
    const float* W2  = (const float*)d_in[6];
    const float* b2  = (const float*)d_in[7];
    const float* g2  = (const float*)d_in[8];
    const float* be2 = (const float*)d_in[9];
    const float* W3  = (const float*)d_in[10];
    const float* b3  = (const float*)d_in[11];
    const float* g3  = (const float*)d_in[12];
    const float* be3 = (const float*)d_in[13];
    const float* W4  = (const float*)d_in[14];
    const float* b4  = (const float*)d_in[15];
    float* out = (float*)d_out;

    float *a1, *a2, *a3, *wt;
    cudaGetSymbolAddress((void**)&a1, g_a1);
    cudaGetSymbolAddress((void**)&a2, g_a2);
    cudaGetSymbolAddress((void**)&a3, g_a3);
    cudaGetSymbolAddress((void**)&wt, g_wtiles);
    float* wt1 = wt;            // L1: 2 tiles
    float* wt2 = wt + 16384;    // L2: 8 tiles
    float* wt3 = wt + 81920;    // L3: 8 tiles

    cudaFuncSetAttribute(gemm_tc<50,  false>, cudaFuncAttributeMaxDynamicSharedMemorySize, GEMM_SMEM);
    cudaFuncSetAttribute(gemm_tc<128, true >, cudaFuncAttributeMaxDynamicSharedMemorySize, GEMM_SMEM);
    cudaFuncSetAttribute(gemm_tc<256, true >, cudaFuncAttributeMaxDynamicSharedMemorySize, GEMM_SMEM);

    prep_w<<<dim3(2, 1), 256>>>(W1, wt1, 50, 128);
    prep_w<<<dim3(4, 2), 256>>>(W2, wt2, 128, 256);
    prep_w<<<dim3(8, 1), 256>>>(W3, wt3, 256, 128);

    gemm_tc<50,  false><<<dim3(NPB, 1), 512, GEMM_SMEM>>>(z,  W1, wt1, b1, a1, 128);
    stats_kernel<<<128, 128>>>(g1, be1, 128);
    gemm_tc<128, true ><<<dim3(NPB, 2), 512, GEMM_SMEM>>>(a1, W2, wt2, b2, a2, 256);
    stats_kernel<<<256, 128>>>(g2, be2, 256);
    gemm_tc<256, true ><<<dim3(NPB, 1), 512, GEMM_SMEM>>>(a2, W3, wt3, b3, a3, 128);
    stats_kernel<<<128, 128>>>(g3, be3, 128);
    final_kernel<<<512, 256>>>(W4, b4, u, out);
}

// round 9
// speedup vs baseline: 1.1466x; 1.0358x over previous
#include <cuda_runtime.h>
#include <cstdint>
#include <math_constants.h>

#define BATCH 131072
#define RPB   256              /* rows per CTA */
#define NPB   (BATCH / RPB)    /* 512 row blocks */

#if defined(__CUDA_ARCH_FEAT_SM103_ALL) || defined(__CUDA_ARCH_FEAT_SM100_ALL) || defined(__CUDA_ARCH_FEAT_SM101_ALL)
#define HAS_TCGEN05 1
#else
#define HAS_TCGEN05 0
#endif

// ---------------- scratch ----------------------------------------------------
__device__ float g_a1[BATCH * 128];
__device__ float g_a2[BATCH * 256];
__device__ float g_a3[BATCH * 128];
__device__ float g_psum[256 * NPB];   // column-major: [col][rowblock]
__device__ float g_psq [256 * NPB];
__device__ float g_scale[256];
__device__ float g_shift[256];
__device__ float g_wtiles[147456];    // preformatted W tiles (8192 floats each)

// ---------------- ptx helpers -------------------------------------------------
__device__ __forceinline__ uint32_t smem_u32(const void* p) {
    uint32_t a;
    asm("{ .reg .u64 t; cvta.to.shared.u64 t, %1; cvt.u32.u64 %0, t; }" : "=r"(a) : "l"(p));
    return a;
}

#if HAS_TCGEN05
__device__ __forceinline__ uint32_t elect1() {
    uint32_t p;
    asm volatile("{\n\t.reg .pred p;\n\telect.sync _|p, 0xFFFFFFFF;\n\tselp.b32 %0, 1, 0, p;\n\t}" : "=r"(p));
    return p;
}
#define TCGEN05_ALLOC(smem_addr, nCols) \
    asm volatile("tcgen05.alloc.cta_group::1.sync.aligned.shared::cta.b32 [%0], %1;" \
                 :: "r"((uint32_t)(smem_addr)), "r"((uint32_t)(nCols)) : "memory")
#define TCGEN05_DEALLOC(tmem_addr, nCols) \
    asm volatile("tcgen05.dealloc.cta_group::1.sync.aligned.b32 %0, %1;" \
                 :: "r"(tmem_addr), "r"((uint32_t)(nCols)))
#define TCGEN05_RELINQ() \
    asm volatile("tcgen05.relinquish_alloc_permit.cta_group::1.sync.aligned;")
#define TCGEN05_COMMIT(mbar_smem_addr) \
    asm volatile("tcgen05.commit.cta_group::1.mbarrier::arrive::one.shared::cluster.b64 [%0];" \
                 :: "r"((uint32_t)(mbar_smem_addr)) : "memory")
#define TCGEN05_FENCE_AFTER() \
    asm volatile("tcgen05.fence::after_thread_sync;" ::: "memory")
#define TCGEN05_FENCE_BEFORE() \
    asm volatile("tcgen05.fence::before_thread_sync;" ::: "memory")
#define TCGEN05_WAIT_LD() \
    asm volatile("tcgen05.wait::ld.sync.aligned;" ::: "memory")
#define MBARRIER_INIT(mbar_smem_addr, count) \
    asm volatile("mbarrier.init.shared.b64 [%0], %1;" \
                 :: "r"((uint32_t)(mbar_smem_addr)), "r"((uint32_t)(count)) : "memory")
#define MBARRIER_WAIT_PARITY(mbar_smem_addr, phase_parity) do { \
    uint32_t _mbar = (uint32_t)(mbar_smem_addr); \
    uint32_t _parity = (uint32_t)(phase_parity); \
    uint32_t _done; \
    asm volatile("{\n\t.reg .pred p;\n\t" \
        "mbarrier.try_wait.parity.acquire.cta.shared::cta.b64 p, [%1], %2;\n\t" \
        "selp.b32 %0, 1, 0, p;\n\t}" \
        : "=r"(_done) : "r"(_mbar), "r"(_parity) : "memory"); \
    if (!_done) { \
        asm volatile("{\n\t.reg .pred P1;\n\t" \
            "WAIT_LOOP_%=:\n\t" \
            "mbarrier.try_wait.parity.acquire.cta.shared::cta.b64 P1, [%0], %1, 0x989680;\n\t" \
            "@P1 bra.uni WAIT_DONE_%=;\n\t" \
            "bra.uni WAIT_LOOP_%=;\n\t" \
            "WAIT_DONE_%=:\n\t}" \
            :: "r"(_mbar), "r"(_parity) : "memory"); \
    } \
} while (0)
#define TCGEN05_LD_32X32B_X32(r, tmem_addr) \
    asm volatile("tcgen05.ld.sync.aligned.32x32b.x32.b32 " \
        "{%0, %1, %2, %3, %4, %5, %6, %7, " \
        " %8, %9, %10, %11, %12, %13, %14, %15, " \
        " %16, %17, %18, %19, %20, %21, %22, %23, " \
        " %24, %25, %26, %27, %28, %29, %30, %31}, [%32];" \
        : "=r"((r)[0]),  "=r"((r)[1]),  "=r"((r)[2]),  "=r"((r)[3]), \
          "=r"((r)[4]),  "=r"((r)[5]),  "=r"((r)[6]),  "=r"((r)[7]), \
          "=r"((r)[8]),  "=r"((r)[9]),  "=r"((r)[10]), "=r"((r)[11]), \
          "=r"((r)[12]), "=r"((r)[13]), "=r"((r)[14]), "=r"((r)[15]), \
          "=r"((r)[16]), "=r"((r)[17]), "=r"((r)[18]), "=r"((r)[19]), \
          "=r"((r)[20]), "=r"((r)[21]), "=r"((r)[22]), "=r"((r)[23]), \
          "=r"((r)[24]), "=r"((r)[25]), "=r"((r)[26]), "=r"((r)[27]), \
          "=r"((r)[28]), "=r"((r)[29]), "=r"((r)[30]), "=r"((r)[31]) \
        : "r"(tmem_addr))

__device__ __forceinline__ uint64_t sdesc(uint32_t addr) {
    return ((uint64_t)2 << 61) | ((uint64_t)1 << 46) | ((uint64_t)64 << 32) |
           ((uint64_t)1 << 16) | ((uint64_t)(addr >> 4) & 0x3FFF);
}
__device__ __forceinline__ void mma_tf32_ss(uint32_t d, uint64_t ad, uint64_t bd,
                                            uint32_t idesc, uint32_t en) {
    asm volatile("{\n\t.reg .pred p;\n\tsetp.ne.u32 p, %4, 0;\n\t"
        "tcgen05.mma.cta_group::1.kind::tf32 [%0], %1, %2, %3, {%5, %5, %5, %5}, p;\n\t}"
        :: "r"(d), "l"(ad), "l"(bd), "r"(idesc), "r"(en), "r"(0u) : "memory");
}
#endif // HAS_TCGEN05

#define SW128(o) ((o) ^ (((o) >> 3) & 0x70))

// smem layout (after 1KB alignment pad):
//   0      stage0: A0h A0l A1h A1l Bh Bl (16KB each) = 96KB
//   98304  stage1 (96KB)
//   epilogue: 4 slabs of 128x68 floats at wg*36864 (reuse dead fill stages)
//   196608 sSc(1K) 197632 sSh(1K) 198656 sB(512) 199168 redS(8K) 207360 redQ(8K)
#define STAGE_SZ 98304
#define GEMM_SMEM (216 * 1024)

// ---------------------------------------------------------------------------
// prep_all: one launch formats all W tiles (tf32 hi/lo split, SW128 image).
// blocks 0-1: W1 (K=50,N=128); 2-9: W2 (K=128,N=256); 10-17: W3 (K=256,N=128)
// ---------------------------------------------------------------------------
__global__ void prep_all(const float* __restrict__ W1, const float* __restrict__ W2,
                         const float* __restrict__ W3, float* __restrict__ wt)
{
    const int b = blockIdx.x;
    const float* W; float* dst; int Kdim, N, ch, cb, NCH;
    if (b < 2)       { W = W1; dst = wt;         Kdim = 50;  N = 128; NCH = 2; ch = b;             cb = 0; }
    else if (b < 10) { W = W2; dst = wt + 16384; Kdim = 128; N = 256; NCH = 4; ch = (b - 2) & 3;   cb = (b - 2) >> 2; }
    else             { W = W3; dst = wt + 81920; Kdim = 256; N = 128; NCH = 8; ch = b - 10;        cb = 0; }

    char* tile = (char*)(dst + (size_t)(cb * NCH + ch) * 8192);
    const int tid = threadIdx.x;
#pragma unroll
    for (int e = 0; e < 16; e++) {
        int idx = tid + e * 256;
        int n = idx >> 5, kk = idx & 31;
        int k = ch * 32 + kk;
        float v = (k < Kdim) ? W[(size_t)k * N + cb * 128 + n] : 0.f;
        uint32_t hb; asm("cvt.rna.tf32.f32 %0, %1;" : "=r"(hb) : "f"(v));
        float lo = v - __uint_as_float(hb);
        uint32_t off = SW128((uint32_t)(n * 128 + kk * 4));
        *(uint32_t*)(tile + off)         = hb;
        *(float*)   (tile + 16384 + off) = lo;
    }
}

// ---------------------------------------------------------------------------
// GEMM: 512 threads, M=256/CTA, two-stage double buffer, tcgen05 3xTF32.
// Epilogue: 4 warpgroups handle 4 (row-tile, col-half) quadrants in parallel;
// fused vectorized store + stats (LDS.128 -> STG.128 + FFMA).
// ---------------------------------------------------------------------------
template<int KDIM, bool ACT>
__global__ __launch_bounds__(512, 1)
void gemm_tc(const float* __restrict__ A, const float* __restrict__ W,
             const float* __restrict__ wt, const float* __restrict__ bias,
             float* __restrict__ C, int N)
{
#if HAS_TCGEN05
    constexpr int NCH = (KDIM + 31) / 32;
    extern __shared__ char dsm[];
    const uint32_t sb0 = smem_u32(dsm);
    const uint32_t pad = ((sb0 + 1023) & ~1023u) - sb0;
    char* bp = dsm + pad;
    const uint32_t sbu = sb0 + pad;

    float* sSc  = (float*)(bp + 196608);
    float* sSh  = (float*)(bp + 197632);
    float* sB   = (float*)(bp + 198656);
    float* redS = (float*)(bp + 199168);   // 32 groups x 64 cols
    float* redQ = (float*)(bp + 207360);

    __shared__ uint64_t s_mbar[2];
    __shared__ uint32_t s_tptr;
    const uint32_t mbA[2] = { smem_u32(&s_mbar[0]), smem_u32(&s_mbar[1]) };

    const int tid  = threadIdx.x;
    const int wid  = tid >> 5;
    const int lane = tid & 31;
    const int row0 = blockIdx.x * RPB;
    const int col0 = blockIdx.y * 128;

    if (ACT) {
        for (int i = tid; i < KDIM; i += 512) { sSc[i] = g_scale[i]; sSh[i] = g_shift[i]; }
    }
    for (int i = tid; i < 128; i += 512) sB[i] = bias[col0 + i];
    if (tid == 0) { MBARRIER_INIT(mbA[0], 1); MBARRIER_INIT(mbA[1], 1); }
    if (wid == 0) TCGEN05_ALLOC(smem_u32(&s_tptr), 256);
    __syncthreads();
    const uint32_t tmem = s_tptr;

    const uint32_t IDESC = (1u << 4) | (2u << 7) | (2u << 10) | (16u << 17) | (8u << 24);

    for (int ch = 0; ch < NCH; ch++) {
        const int st  = ch & 1;
        const int use = ch >> 1;
        if (use >= 1) { MBARRIER_WAIT_PARITY(mbA[st], (use - 1) & 1); }

        char* ps = bp + st * STAGE_SZ;
        const int k0 = ch * 32;

        // ---- B copy: preformatted 32KB tile ----
        {
            const float4* src = (const float4*)(wt + (size_t)(blockIdx.y * NCH + ch) * 8192);
            float4* dst = (float4*)(ps + 65536);
#pragma unroll
            for (int i = 0; i < 4; i++) dst[tid + i * 512] = src[tid + i * 512];
        }
        // ---- A fill: two 128-row tiles ----
#pragma unroll
        for (int t = 0; t < 2; t++) {
            char* pAh = ps + t * 32768;
            char* pAl = pAh + 16384;
            const int rbase = row0 + t * 128;
            if (KDIM % 4 == 0) {
#pragma unroll
                for (int e = 0; e < 2; e++) {
                    int f = tid + e * 512;
                    int m = f >> 3, kq = f & 7;
                    float4 v4 = *(const float4*)(A + (size_t)(rbase + m) * KDIM + k0 + kq * 4);
                    float vv[4] = {v4.x, v4.y, v4.z, v4.w};
                    uint32_t hi[4]; float lo[4];
#pragma unroll
                    for (int u = 0; u < 4; u++) {
                        float v = vv[u];
                        if (ACT) {
                            int k = k0 + kq * 4 + u;
                            v = fmaf(v, sSc[k], sSh[k]);
                            v = v > 0.f ? v : 0.2f * v;
                        }
                        asm("cvt.rna.tf32.f32 %0, %1;" : "=r"(hi[u]) : "f"(v));
                        lo[u] = v - __uint_as_float(hi[u]);
                    }
                    uint32_t off = SW128((uint32_t)(m * 128 + kq * 16));
                    *(uint4*)(pAh + off)  = make_uint4(hi[0], hi[1], hi[2], hi[3]);
                    *(float4*)(pAl + off) = make_float4(lo[0], lo[1], lo[2], lo[3]);
                }
            } else {
#pragma unroll
                for (int i = 0; i < 8; i++) {
                    int idx = tid + i * 512;
                    int m = idx >> 5, kk = idx & 31, k = k0 + kk;
                    float v = 0.f;
                    if (k < KDIM) {
                        v = A[(size_t)(rbase + m) * KDIM + k];
                        if (ACT) {
                            v = fmaf(v, sSc[k], sSh[k]);
                            v = v > 0.f ? v : 0.2f * v;
                        }
                    }
                    uint32_t hb; asm("cvt.rna.tf32.f32 %0, %1;" : "=r"(hb) : "f"(v));
                    float lo = v - __uint_as_float(hb);
                    uint32_t off = SW128((uint32_t)(m * 128 + kk * 4));
                    *(uint32_t*)(pAh + off) = hb;
                    *(float*)   (pAl + off) = lo;
                }
            }
        }
        asm volatile("fence.proxy.async.shared::cta;" ::: "memory");
        __syncthreads();

        if (wid == 0 && elect1()) {
            const uint32_t sbase = sbu + st * STAGE_SZ;
            uint64_t bdh = sdesc(sbase + 65536), bdl = sdesc(sbase + 81920);
#pragma unroll
            for (int t = 0; t < 2; t++) {
                uint64_t adh = sdesc(sbase + t * 32768);
                uint64_t adl = sdesc(sbase + t * 32768 + 16384);
                uint32_t dofs = tmem + t * 128;
#pragma unroll
                for (int ks = 0; ks < 4; ks++) {
                    uint32_t en0 = (ch == 0 && ks == 0) ? 0u : 1u;
                    mma_tf32_ss(dofs, adh + ks * 2, bdh + ks * 2, IDESC, en0);
                    mma_tf32_ss(dofs, adh + ks * 2, bdl + ks * 2, IDESC, 1u);
                    mma_tf32_ss(dofs, adl + ks * 2, bdh + ks * 2, IDESC, 1u);
                }
            }
            TCGEN05_COMMIT(mbA[st]);
        }
    }
    MBARRIER_WAIT_PARITY(mbA[(NCH - 1) & 1], ((NCH - 1) >> 1) & 1);
    TCGEN05_FENCE_AFTER();
    __syncthreads();   // fill stages dead; reuse as epilogue staging

    // ---- epilogue: 4 warpgroups, one (row-tile t, col-half h) quadrant each
    {
        const int wg     = wid >> 2;       // 0..3
        const int rw     = wid & 3;        // warp within wg
        const int wg_tid = tid & 127;
        const int t = wg >> 1, h = wg & 1;
        float* stage = (float*)(bp + wg * 36864);   // 128 x 68 floats

        // phase 1: TMEM -> staging (bias added), STS.128
#pragma unroll
        for (int half = 0; half < 2; half++) {
            uint32_t regs[32];
            TCGEN05_LD_32X32B_X32(regs, tmem + t * 128 + h * 64 + half * 32);
            TCGEN05_WAIT_LD();
            const int row = rw * 32 + lane;
#pragma unroll
            for (int j4 = 0; j4 < 8; j4++) {
                int cb = half * 32 + j4 * 4;
                float4 v = make_float4(
                    __uint_as_float(regs[j4 * 4 + 0]) + sB[h * 64 + cb + 0],
                    __uint_as_float(regs[j4 * 4 + 1]) + sB[h * 64 + cb + 1],
                    __uint_as_float(regs[j4 * 4 + 2]) + sB[h * 64 + cb + 2],
                    __uint_as_float(regs[j4 * 4 + 3]) + sB[h * 64 + cb + 3]);
                *(float4*)(stage + row * 68 + cb) = v;
            }
        }
        TCGEN05_FENCE_BEFORE();
        asm volatile("bar.sync %0, 128;" :: "r"(wg + 1) : "memory");

        // phase 2: fused coalesced store + 4-col stats partials
        const int cq = wg_tid & 15;     // col quad (4 cols)
        const int rg = wg_tid >> 4;     // row group 0..7
        float sA[4] = {0.f, 0.f, 0.f, 0.f};
        float qA[4] = {0.f, 0.f, 0.f, 0.f};
#pragma unroll 4
        for (int it = 0; it < 16; it++) {
            int r = it * 8 + rg;
            float4 v = *(const float4*)(stage + r * 68 + cq * 4);
            *(float4*)&C[(size_t)(row0 + t * 128 + r) * N + col0 + h * 64 + cq * 4] = v;
            sA[0] += v.x; qA[0] = fmaf(v.x, v.x, qA[0]);
            sA[1] += v.y; qA[1] = fmaf(v.y, v.y, qA[1]);
            sA[2] += v.z; qA[2] = fmaf(v.z, v.z, qA[2]);
            sA[3] += v.w; qA[3] = fmaf(v.w, v.w, qA[3]);
        }
        *(float4*)&redS[(wg * 8 + rg) * 64 + cq * 4] = make_float4(sA[0], sA[1], sA[2], sA[3]);
        *(float4*)&redQ[(wg * 8 + rg) * 64 + cq * 4] = make_float4(qA[0], qA[1], qA[2], qA[3]);
        __syncthreads();
        if (tid < 128) {
            const int hh = tid >> 6, colin = tid & 63;
            float s = 0.f, q = 0.f;
#pragma unroll
            for (int tt = 0; tt < 2; tt++) {
                const int wgi = tt * 2 + hh;
#pragma unroll
                for (int rr = 0; rr < 8; rr++) {
                    s += redS[(wgi * 8 + rr) * 64 + colin];
                    q += redQ[(wgi * 8 + rr) * 64 + colin];
                }
            }
            int c = col0 + tid;
            g_psum[(size_t)c * NPB + blockIdx.x] = s;
            g_psq [(size_t)c * NPB + blockIdx.x] = q;
        }
    }

    __syncthreads();
    if (wid == 0) { TCGEN05_RELINQ(); TCGEN05_DEALLOC(tmem, 256); }

#else
    // ======================= FFMA fallback (plain sm_103 pass) ============
    extern __shared__ char dsm[];
    float (*As)[128] = (float(*)[128])dsm;
    float (*Ws)[128] = (float(*)[128])(dsm + 8192);
    float* sSc = (float*)(dsm + 16384);
    float* sSh = (float*)(dsm + 17408);

    const int tid  = threadIdx.x;
    const int col0 = blockIdx.y * 128;

    if (ACT) {
        for (int i = tid; i < KDIM; i += 512) { sSc[i] = g_scale[i]; sSh[i] = g_shift[i]; }
        __syncthreads();
    }
    const int ty = tid >> 4;
    const int tx = tid & 15;
    float bj[8];
#pragma unroll
    for (int j = 0; j < 8; j++) bj[j] = bias[col0 + tx * 8 + j];

    float cs[8], cq[8];
#pragma unroll
    for (int j = 0; j < 8; j++) { cs[j] = 0.f; cq[j] = 0.f; }

#pragma unroll 1
    for (int rt = 0; rt < 2; rt++) {
        const int row0 = blockIdx.x * RPB + rt * 128;
        float acc[4][8];
#pragma unroll
        for (int i = 0; i < 4; i++)
#pragma unroll
            for (int j = 0; j < 8; j++) acc[i][j] = 0.f;

        for (int k0 = 0; k0 < KDIM; k0 += 16) {
#pragma unroll
            for (int l = 0; l < 4; l++) {
                int idx = tid + l * 512;
                int m = idx >> 4, kk = idx & 15;
                int k = k0 + kk;
                float v = 0.f;
                if ((KDIM % 16 == 0) || k < KDIM) {
                    v = A[(size_t)(row0 + m) * KDIM + k];
                    if (ACT) {
                        v = fmaf(v, sSc[k], sSh[k]);
                        v = v > 0.f ? v : 0.2f * v;
                    }
                }
                As[kk][m] = v;
            }
#pragma unroll
            for (int l = 0; l < 4; l++) {
                int idx = tid + l * 512;
                int kk = idx >> 7, n = idx & 127;
                int k = k0 + kk;
                Ws[kk][n] = ((KDIM % 16 == 0) || k < KDIM) ? W[(size_t)k * N + col0 + n] : 0.f;
            }
            __syncthreads();
#pragma unroll
            for (int kk = 0; kk < 16; kk++) {
                float4 a0 = *(const float4*)&As[kk][ty * 4];
                float4 w0 = *(const float4*)&Ws[kk][tx * 8];
                float4 w1 = *(const float4*)&Ws[kk][tx * 8 + 4];
                float a[4] = {a0.x, a0.y, a0.z, a0.w};
                float w[8] = {w0.x, w0.y, w0.z, w0.w, w1.x, w1.y, w1.z, w1.w};
#pragma unroll
                for (int i = 0; i < 4; i++)
#pragma unroll
                    for (int j = 0; j < 8; j++)
                        acc[i][j] = fmaf(a[i], w[j], acc[i][j]);
            }
            __syncthreads();
        }
#pragma unroll
        for (int i = 0; i < 4; i++) {
            float v[8];
#pragma unroll
            for (int j = 0; j < 8; j++) {
                v[j] = acc[i][j] + bj[j];
                cs[j] += v[j];
                cq[j] = fmaf(v[j], v[j], cq[j]);
            }
            float* cptr = &C[(size_t)(row0 + ty * 4 + i) * N + col0 + tx * 8];
            *(float4*)cptr       = make_float4(v[0], v[1], v[2], v[3]);
            *(float4*)(cptr + 4) = make_float4(v[4], v[5], v[6], v[7]);
        }
        __syncthreads();
    }

    float* red = &As[0][0];
#pragma unroll
    for (int j = 0; j < 8; j++) red[ty * 128 + tx * 8 + j] = cs[j];
    __syncthreads();
    if (tid < 128) {
        float s = 0.f;
#pragma unroll
        for (int r = 0; r < 32; r++) s += red[r * 128 + tid];
        g_psum[(size_t)(col0 + tid) * NPB + blockIdx.x] = s;
    }
    __syncthreads();
#pragma unroll
    for (int j = 0; j < 8; j++) red[ty * 128 + tx * 8 + j] = cq[j];
    __syncthreads();
    if (tid < 128) {
        float s = 0.f;
#pragma unroll
        for (int r = 0; r < 32; r++) s += red[r * 128 + tid];
        g_psq[(size_t)(col0 + tid) * NPB + blockIdx.x] = s;
    }
#endif
}

// ---------------------------------------------------------------------------
__global__ void stats_kernel(const float* __restrict__ gamma,
                             const float* __restrict__ beta, int N)
{
    __shared__ float ss[128], qq[128];
    const int c = blockIdx.x;
    const int t = threadIdx.x;
    const float* bs = g_psum + (size_t)c * NPB;
    const float* bq = g_psq  + (size_t)c * NPB;
    float s = bs[t] + bs[t + 128] + bs[t + 256] + bs[t + 384];
    float q = bq[t] + bq[t + 128] + bq[t + 256] + bq[t + 384];
    ss[t] = s; qq[t] = q;
    __syncthreads();
    for (int off = 64; off > 0; off >>= 1) {
        if (t < off) { ss[t] += ss[t + off]; qq[t] += qq[t + off]; }
        __syncthreads();
    }
    if (t == 0) {
        float mean = ss[0] * (1.0f / (float)BATCH);
        float var  = qq[0] * (1.0f / (float)BATCH) - mean * mean;
        float inv  = rsqrtf(var + 1e-5f);
        float scl  = gamma[c] * inv;
        g_scale[c] = scl;
        g_shift[c] = beta[c] - mean * scl;
    }
}

// ---------------------------------------------------------------------------
__global__ __launch_bounds__(256)
void final_kernel(const float* __restrict__ W4, const float* __restrict__ b4,
                  const float* __restrict__ U, float* __restrict__ out)
{
    __shared__ float w4s[128 * 25];
    __shared__ float b4s[25];
    __shared__ float sc[128], sh[128];
    __shared__ __align__(16) float us[256 * 25];

    const int tid  = threadIdx.x;
    const int row0 = blockIdx.x * 256;
    const int row  = row0 + tid;

    for (int i = tid; i < 128 * 25; i += 256) w4s[i] = W4[i];
    if (tid < 25) b4s[tid] = b4[tid];
    if (tid < 128) { sc[tid] = g_scale[tid]; sh[tid] = g_shift[tid]; }
    __syncthreads();

    float lgt[25];
#pragma unroll
    for (int j = 0; j < 25; j++) lgt[j] = b4s[j];

    const float* arow = g_a3 + (size_t)row * 128;
    for (int k = 0; k < 128; k += 4) {
        float4 a4 = *(const float4*)(arow + k);
        float hv[4] = {a4.x, a4.y, a4.z, a4.w};
#pragma unroll
        for (int t = 0; t < 4; t++) {
            float h = fmaf(hv[t], sc[k + t], sh[k + t]);
            h = h > 0.f ? h : 0.2f * h;
#pragma unroll
            for (int j = 0; j < 25; j++)
                lgt[j] = fmaf(h, w4s[(k + t) * 25 + j], lgt[j]);
        }
    }

    unsigned mask = 0x1FFFFFFu;
#pragma unroll 1
    for (int s = 0; s < 15; s++) {
        __syncthreads();
        const float4* ub4 = (const float4*)(U + ((size_t)s * BATCH + row0) * 25);
        float4* us4 = (float4*)us;
        for (int i = tid; i < 1600; i += 256) us4[i] = ub4[i];
        __syncthreads();

        float best = -CUDART_INF_F;
        int bi = __ffs(mask) - 1;
#pragma unroll
        for (int j = 0; j < 25; j++) {
            if (mask & (1u << j)) {
                float uu = us[tid * 25 + j];
                float nz = -__logf(-__logf(uu));
                float v  = lgt[j] + nz;
                if (v > best) { best = v; bi = j; }
            }
        }
        mask &= ~(1u << bi);
        out[(size_t)row * 15 + s] = (float)bi / 24.0f;
    }
}

// ---------------------------------------------------------------------------
extern "C" void kernel_launch(void* const* d_in, const int* in_sizes, int n_in,
                              void* d_out, int out_size)
{
    const float* z   = (const float*)d_in[0];
    const float* u   = (const float*)d_in[1];
    const float* W1  = (const float*)d_in[2];
    const float* b1  = (const float*)d_in[3];
    const float* g1  = (const float*)d_in[4];
    const float* be1 = (const float*)d_in[5];
    const float* W2  = (const float*)d_in[6];
    const float* b2  = (const float*)d_in[7];
    const float* g2  = (const float*)d_in[8];
    const float* be2 = (const float*)d_in[9];
    const float* W3  = (const float*)d_in[10];
    const float* b3  = (const float*)d_in[11];
    const float* g3  = (const float*)d_in[12];
    const float* be3 = (const float*)d_in[13];
    const float* W4  = (const float*)d_in[14];
    const float* b4  = (const float*)d_in[15];
    float* out = (float*)d_out;

    float *a1, *a2, *a3, *wt;
    cudaGetSymbolAddress((void**)&a1, g_a1);
    cudaGetSymbolAddress((void**)&a2, g_a2);
    cudaGetSymbolAddress((void**)&a3, g_a3);
    cudaGetSymbolAddress((void**)&wt, g_wtiles);
    float* wt1 = wt;            // L1: 2 tiles
    float* wt2 = wt + 16384;    // L2: 8 tiles
    float* wt3 = wt + 81920;    // L3: 8 tiles

    cudaFuncSetAttribute(gemm_tc<50,  false>, cudaFuncAttributeMaxDynamicSharedMemorySize, GEMM_SMEM);
    cudaFuncSetAttribute(gemm_tc<128, true >, cudaFuncAttributeMaxDynamicSharedMemorySize, GEMM_SMEM);
    cudaFuncSetAttribute(gemm_tc<256, true >, cudaFuncAttributeMaxDynamicSharedMemorySize, GEMM_SMEM);

    prep_all<<<18, 256>>>(W1, W2, W3, wt);

    gemm_tc<50,  false><<<dim3(NPB, 1), 512, GEMM_SMEM>>>(z,  W1, wt1, b1, a1, 128);
    stats_kernel<<<128, 128>>>(g1, be1, 128);
    gemm_tc<128, true ><<<dim3(NPB, 2), 512, GEMM_SMEM>>>(a1, W2, wt2, b2, a2, 256);
    stats_kernel<<<256, 128>>>(g2, be2, 256);
    gemm_tc<256, true ><<<dim3(NPB, 1), 512, GEMM_SMEM>>>(a2, W3, wt3, b3, a3, 128);
    stats_kernel<<<128, 128>>>(g3, be3, 128);
    final_kernel<<<512, 256>>>(W4, b4, u, out);
}